// round 8
// baseline (speedup 1.0000x reference)
#include <cuda_runtime.h>
#include <cstdint>

#define B_   32768
#define D_   512
#define E_   10
#define H_   128
#define L_   2
#define RH1_ 256
#define RH2_ 128

__device__ uint32_t g_Xp[8388608];    // x, A-fragment fp16: 256 tiles x 16 ch x 2048
__device__ uint32_t g_Wf[491520];     // weights, B-fragment fp16
__device__ uint32_t g_R1f[4194304];   // router h1, A-fragment fp16: 256 tiles x 8 ch

#define RW1_OFF 0
#define RW2_OFF 65536
#define EW1_OFF 81920
#define EW2_OFF 409600

#define MMA_F16(d, a, bb0, bb1) \
    asm volatile("mma.sync.aligned.m16n8k16.row.col.f32.f16.f16.f32 " \
        "{%0,%1,%2,%3},{%4,%5,%6,%7},{%8,%9},{%0,%1,%2,%3};" \
        : "+f"((d)[0]), "+f"((d)[1]), "+f"((d)[2]), "+f"((d)[3]) \
        : "r"((a).x), "r"((a).y), "r"((a).z), "r"((a).w), "r"(bb0), "r"(bb1))

static __device__ __forceinline__ uint32_t pack_h2(float lo, float hi) {
    uint32_t r;
    asm("cvt.rn.f16x2.f32 %0, %1, %2;" : "=r"(r) : "f"(hi), "f"(lo));
    return r;
}

// fragment slot (u32) for (row, kpair) in a 128-row A chunk
static __device__ __forceinline__ int afrag128(int row, int kp) {
    int ks = kp >> 3, tig = kp & 3, bh = (kp & 7) >> 2;
    int mt = row >> 4, r16 = row & 15, g = r16 & 7, hi = r16 >> 3;
    return (ks * 8 + mt) * 128 + ((g * 4 + tig) << 2) + hi + 2 * bh;
}
// same for a 64-row A chunk (4 m-tiles)
static __device__ __forceinline__ int afrag64(int row, int kp) {
    int ks = kp >> 3, tig = kp & 3, bh = (kp & 7) >> 2;
    int mt = row >> 4, r16 = row & 15, g = r16 & 7, hi = r16 >> 3;
    return (ks * 4 + mt) * 128 + ((g * 4 + tig) << 2) + hi + 2 * bh;
}

// ---- cp.async --------------------------------------------------------------
static __device__ __forceinline__ void cpasync16(uint32_t saddr, const void* g) {
    asm volatile("cp.async.cg.shared.global [%0], [%1], 16;" :: "r"(saddr), "l"(g));
}
#define CP_COMMIT() asm volatile("cp.async.commit_group;" ::: "memory")
#define CP_WAIT2()  asm volatile("cp.async.wait_group 2;" ::: "memory")
#define CP_WAIT0()  asm volatile("cp.async.wait_group 0;" ::: "memory")

// full 2048-u32 chunk (8 KB)
static __device__ __forceinline__ void issue_chunk(uint32_t sbase, const uint32_t* g,
                                                   int tid) {
    cpasync16(sbase + tid * 16, g + tid * 4);
    cpasync16(sbase + 4096 + tid * 16, g + (tid + 256) * 4);
}
// 64-row half of a 128-row A chunk (two 512-u32 pieces -> contiguous 1024 u32)
static __device__ __forceinline__ void issue_chunkA64(uint32_t sbase, const uint32_t* g,
                                                      int h, int tid) {
    const uint32_t* src = (tid < 128) ? (g + h * 512 + tid * 4)
                                      : (g + 1024 + h * 512 + (tid - 128) * 4);
    cpasync16(sbase + tid * 16, src);
}

// ---- MMA cores -------------------------------------------------------------
// 128-row CTA, warp tile 32x64
static __device__ __forceinline__ void compute_bk128(const uint32_t* As, const uint32_t* Bs,
                                                     float (*acc)[8][4],
                                                     int mtg, int ntg, int lane) {
#pragma unroll
    for (int ks = 0; ks < 2; ks++) {
        uint2 b[8];
#pragma unroll
        for (int j = 0; j < 8; j++)
            b[j] = *(const uint2*)&Bs[(ks * 16 + ntg + j) * 64 + lane * 2];
        uint4 a[2];
#pragma unroll
        for (int i = 0; i < 2; i++)
            a[i] = *(const uint4*)&As[(ks * 8 + mtg + i) * 128 + lane * 4];
#pragma unroll
        for (int i = 0; i < 2; i++)
#pragma unroll
            for (int j = 0; j < 8; j++)
                MMA_F16(acc[i][j], a[i], b[j].x, b[j].y);
    }
}
// 64-row CTA, warp tile 16x64
static __device__ __forceinline__ void compute_bk64(const uint32_t* As, const uint32_t* Bs,
                                                    float (*acc)[4],
                                                    int mt, int ntg, int lane) {
#pragma unroll
    for (int ks = 0; ks < 2; ks++) {
        uint2 b[8];
#pragma unroll
        for (int j = 0; j < 8; j++)
            b[j] = *(const uint2*)&Bs[(ks * 16 + ntg + j) * 64 + lane * 2];
        uint4 a = *(const uint4*)&As[(ks * 4 + mt) * 128 + lane * 4];
#pragma unroll
        for (int j = 0; j < 8; j++)
            MMA_F16(acc[j], a, b[j].x, b[j].y);
    }
}

// ---- pipelined mainloops ---------------------------------------------------
static __device__ __forceinline__ void gemm_pipe128(uint32_t aring, uint32_t bring,
                                                    const uint32_t* gA, const uint32_t* gB,
                                                    const uint32_t* Asm, const uint32_t* Bsm,
                                                    int nch, float (*acc)[8][4],
                                                    int mtg, int ntg, int lane, int tid) {
#pragma unroll
    for (int s = 0; s < 3; s++) {
        issue_chunk(aring + s * 8192, gA + s * 2048, tid);
        issue_chunk(bring + s * 8192, gB + s * 2048, tid);
        CP_COMMIT();
    }
#pragma unroll 1
    for (int c = 0; c < nch; c++) {
        CP_WAIT2();
        __syncthreads();
        if (c + 3 < nch) {
            int st = (c + 3) & 3;
            issue_chunk(aring + st * 8192, gA + (c + 3) * 2048, tid);
            issue_chunk(bring + st * 8192, gB + (c + 3) * 2048, tid);
        }
        CP_COMMIT();
        compute_bk128(Asm + (c & 3) * 2048, Bsm + (c & 3) * 2048, acc, mtg, ntg, lane);
    }
}
static __device__ __forceinline__ void gemm_pipe64(uint32_t aring, uint32_t bring,
                                                   const uint32_t* gA, int h,
                                                   const uint32_t* gB,
                                                   const uint32_t* Asm, const uint32_t* Bsm,
                                                   int nch, float (*acc)[4],
                                                   int mt, int ntg, int lane, int tid) {
#pragma unroll
    for (int s = 0; s < 3; s++) {
        issue_chunkA64(aring + s * 4096, gA + s * 2048, h, tid);
        issue_chunk(bring + s * 8192, gB + s * 2048, tid);
        CP_COMMIT();
    }
#pragma unroll 1
    for (int c = 0; c < nch; c++) {
        CP_WAIT2();
        __syncthreads();
        if (c + 3 < nch) {
            int st = (c + 3) & 3;
            issue_chunkA64(aring + st * 4096, gA + (c + 3) * 2048, h, tid);
            issue_chunk(bring + st * 8192, gB + (c + 3) * 2048, tid);
        }
        CP_COMMIT();
        compute_bk64(Asm + (c & 3) * 1024, Bsm + (c & 3) * 2048, acc, mt, ntg, lane);
    }
}

// ---- prep: x -> A-fragment fp16 (smem staged, coalesced reads) -------------
__global__ __launch_bounds__(256)
void prep_x(const float* __restrict__ x, uint32_t* __restrict__ xp) {
    __shared__ float tile[128][33];
    const int tid = threadIdx.x;
    const int rt = blockIdx.x >> 4, c = blockIdx.x & 15;
#pragma unroll
    for (int t = 0; t < 4; t++) {
        int idx = tid + t * 256;
        int row = idx >> 3, q = (idx & 7) * 4;
        float4 v = *(const float4*)&x[(size_t)(rt * 128 + row) * D_ + c * 32 + q];
        tile[row][q] = v.x; tile[row][q + 1] = v.y;
        tile[row][q + 2] = v.z; tile[row][q + 3] = v.w;
    }
    __syncthreads();
    uint32_t* dst = xp + ((size_t)rt * 16 + c) * 2048 + tid * 8;
    uint32_t r8[8];
#pragma unroll
    for (int j = 0; j < 8; j++) {
        int w = tid * 8 + j;
        int slot = w >> 7, ks = slot >> 3, mt = slot & 7;
        int within = w & 127, lane = within >> 2, r = within & 3;
        int g = lane >> 2, tig = lane & 3, hi = r & 1, bh = r >> 1;
        int row = mt * 16 + hi * 8 + g;
        int k = (ks * 8 + bh * 4 + tig) * 2;
        r8[j] = pack_h2(tile[row][k], tile[row][k + 1]);
    }
    *(uint4*)dst       = make_uint4(r8[0], r8[1], r8[2], r8[3]);
    *(uint4*)(dst + 4) = make_uint4(r8[4], r8[5], r8[6], r8[7]);
}

// ---- prep: all weights -> B-fragment fp16 ---------------------------------
__global__ __launch_bounds__(256)
void prep_w(const float* __restrict__ rw1, const float* __restrict__ rw2,
            const float* __restrict__ ew1, const float* __restrict__ ew2,
            uint32_t* __restrict__ wp) {
    int id = blockIdx.x * 256 + threadIdx.x;
    int w = id & 2047;
    int slot = w >> 6, ks = slot >> 4, nt = slot & 15;
    int within = w & 63, lane = within >> 1, r = within & 1;
    int g = lane >> 2, tig = lane & 3;
    int nl = nt * 8 + g;
    int kk = ks * 16 + (r * 4 + tig) * 2;
    float v0, v1;
    if (id < 65536) {
        int ch = id >> 11, nb = ch >> 4, c = ch & 15;
        int n = nb * 128 + nl, k = c * 32 + kk;
        v0 = rw1[k * RH1_ + n]; v1 = rw1[(k + 1) * RH1_ + n];
    } else if (id < 81920) {
        int c = (id - 65536) >> 11, k = c * 32 + kk;
        v0 = rw2[k * RH2_ + nl]; v1 = rw2[(k + 1) * RH2_ + nl];
    } else if (id < 409600) {
        int t = id - 81920, e = t >> 15, c = (t >> 11) & 15, k = c * 32 + kk;
        v0 = ew1[(size_t)e * 65536 + k * H_ + nl];
        v1 = ew1[(size_t)e * 65536 + (k + 1) * H_ + nl];
    } else {
        int t = id - 409600, e = t >> 13, c = (t >> 11) & 3, k = c * 32 + kk;
        v0 = ew2[(size_t)e * 16384 + k * H_ + nl];
        v1 = ew2[(size_t)e * 16384 + (k + 1) * H_ + nl];
    }
    wp[id] = pack_h2(v0, v1);
}

// ---- router GEMM1 (128-row tiles): Xp @ rw1 -> R1f, bias+relu --------------
__global__ __launch_bounds__(256)
void router1_f16(const uint32_t* __restrict__ Xp, const uint32_t* __restrict__ Wp,
                 const float* __restrict__ rb1, uint32_t* __restrict__ R1f) {
    extern __shared__ uint32_t sm[];
    uint32_t* Asm = sm;
    uint32_t* Bsm = sm + 8192;
    float* bs = (float*)(sm + 16384);
    uint32_t aring = (uint32_t)__cvta_generic_to_shared(Asm);
    uint32_t bring = (uint32_t)__cvta_generic_to_shared(Bsm);

    const int tid = threadIdx.x, lane = tid & 31, wid = tid >> 5;
    const int bx = blockIdx.x, nb = blockIdx.y, cb = nb * 128;
    const int mtg = (wid & 3) * 2, ntg = (wid >> 2) * 8;
    if (tid < 128) bs[tid] = rb1[cb + tid];

    float acc[2][8][4];
#pragma unroll
    for (int i = 0; i < 2; i++)
#pragma unroll
        for (int j = 0; j < 8; j++)
#pragma unroll
            for (int q = 0; q < 4; q++) acc[i][j][q] = 0.f;

    gemm_pipe128(aring, bring, Xp + (size_t)bx * 16 * 2048,
                 Wp + (size_t)nb * 16 * 2048, Asm, Bsm, 16, acc, mtg, ntg, lane, tid);

    const int g = lane >> 2, tig = lane & 3;
    const int mrow = (wid & 3) * 32, nh = wid >> 2;
#pragma unroll
    for (int i = 0; i < 2; i++)
#pragma unroll
        for (int j = 0; j < 8; j++) {
            int nl = nh * 64 + j * 8 + 2 * tig;
            float b0 = bs[nl], b1 = bs[nl + 1];
            float v00 = fmaxf(acc[i][j][0] + b0, 0.f);
            float v01 = fmaxf(acc[i][j][1] + b1, 0.f);
            float v10 = fmaxf(acc[i][j][2] + b0, 0.f);
            float v11 = fmaxf(acc[i][j][3] + b1, 0.f);
            int r0 = mrow + i * 16 + g, r1 = r0 + 8;
            int n = cb + nl;
            int ch = n >> 5, kp = (n & 31) >> 1;
            size_t base = ((size_t)bx * 8 + ch) * 2048;
            R1f[base + afrag128(r0, kp)] = pack_h2(v00, v01);
            R1f[base + afrag128(r1, kp)] = pack_h2(v10, v11);
        }
}

// ---- router GEMM2 + logits + gumbel (64-row tiles) -------------------------
__global__ __launch_bounds__(256, 3)
void router23_f16(const uint32_t* __restrict__ R1f, const uint32_t* __restrict__ Wp,
                  const float* __restrict__ rb2, const float* __restrict__ rw3,
                  const float* __restrict__ rb3, const float* __restrict__ u,
                  float* __restrict__ weights) {
    extern __shared__ uint32_t sm[];
    uint32_t* Asm = sm;                  // 4 x 1024
    uint32_t* Bsm = sm + 4096;           // 4 x 2048
    float* bs   = (float*)(sm + 12288);  // 128
    float* b3   = (float*)(sm + 12416);  // 16
    float* w3s  = (float*)(sm + 12432);  // 1280
    float* zbuf = (float*)(sm + 13712);  // 1280
    uint32_t aring = (uint32_t)__cvta_generic_to_shared(Asm);
    uint32_t bring = (uint32_t)__cvta_generic_to_shared(Bsm);

    const int tid = threadIdx.x, lane = tid & 31, wid = tid >> 5;
    const int bx = blockIdx.x;
    const int mt = wid & 3, ntg = (wid >> 2) * 8;
    if (tid < 128) bs[tid] = rb2[tid];
    if (tid < E_)  b3[tid] = rb3[tid];
    for (int i = tid; i < RH2_ * E_; i += 256) w3s[i] = rw3[i];

    float acc[8][4];
#pragma unroll
    for (int j = 0; j < 8; j++)
#pragma unroll
        for (int q = 0; q < 4; q++) acc[j][q] = 0.f;

    gemm_pipe64(aring, bring, R1f + (size_t)(bx >> 1) * 8 * 2048, bx & 1,
                Wp, Asm, Bsm, 8, acc, mt, ntg, lane, tid);

    const int g = lane >> 2, tig = lane & 3;
    const int nh = wid >> 2;
    float zp[2][E_];
#pragma unroll
    for (int h = 0; h < 2; h++)
#pragma unroll
        for (int e = 0; e < E_; e++) zp[h][e] = 0.f;

#pragma unroll
    for (int j = 0; j < 8; j++) {
        int nl0 = nh * 64 + j * 8 + 2 * tig, nl1 = nl0 + 1;
        float v00 = fmaxf(acc[j][0] + bs[nl0], 0.f);
        float v01 = fmaxf(acc[j][1] + bs[nl1], 0.f);
        float v10 = fmaxf(acc[j][2] + bs[nl0], 0.f);
        float v11 = fmaxf(acc[j][3] + bs[nl1], 0.f);
#pragma unroll
        for (int e = 0; e < E_; e++) {
            float wA = w3s[nl0 * E_ + e], wB = w3s[nl1 * E_ + e];
            zp[0][e] += v00 * wA + v01 * wB;
            zp[1][e] += v10 * wA + v11 * wB;
        }
    }
#pragma unroll
    for (int h = 0; h < 2; h++)
#pragma unroll
        for (int e = 0; e < E_; e++) {
            zp[h][e] += __shfl_xor_sync(0xFFFFFFFFu, zp[h][e], 1);
            zp[h][e] += __shfl_xor_sync(0xFFFFFFFFu, zp[h][e], 2);
        }
    if (tig == 0) {
#pragma unroll
        for (int h = 0; h < 2; h++) {
            int row = mt * 16 + h * 8 + g;
#pragma unroll
            for (int e = 0; e < E_; e++)
                zbuf[(nh * 64 + row) * E_ + e] = zp[h][e];
        }
    }
    __syncthreads();
    if (tid < 64) {
        int b = bx * 64 + tid;
        float lg[E_], mx = -1e30f;
#pragma unroll
        for (int e = 0; e < E_; e++) {
            float uu = u[(size_t)b * E_ + e];
            uu = fminf(fmaxf(uu, 1e-10f), 1.0f);
            float gg = -logf(-logf(uu) + 1e-10f);
            lg[e] = (zbuf[tid * E_ + e] + zbuf[(64 + tid) * E_ + e] + b3[e] + gg)
                    * (1.0f / 3.0f);
            mx = fmaxf(mx, lg[e]);
        }
        float sum = 0.f;
#pragma unroll
        for (int e = 0; e < E_; e++) { lg[e] = expf(lg[e] - mx); sum += lg[e]; }
        float inv = 1.f / sum;
#pragma unroll
        for (int e = 0; e < E_; e++) weights[(size_t)b * E_ + e] = lg[e] * inv;
    }
}

// ---- fused expert chain (64-row tiles, occ 3) ------------------------------
__global__ __launch_bounds__(256, 3)
void expert_f16(const uint32_t* __restrict__ Xp, const uint32_t* __restrict__ Wp,
                const float* __restrict__ eb1, const float* __restrict__ eb2,
                const float* __restrict__ ew3, const float* __restrict__ eb3,
                float* __restrict__ chart) {
    extern __shared__ uint32_t sm[];
    uint32_t* Asm = sm;                   // 4 x 1024
    uint32_t* Bsm = sm + 4096;            // 4 x 2048
    uint32_t* H1  = sm + 12288;           // 4 x 1024 (h1, 64-row A-fragments)
    float* b1s  = (float*)(sm + 16384);   // 128
    float* b2s  = (float*)(sm + 16512);   // 128
    float* w3s  = (float*)(sm + 16640);   // 256
    float* zbuf = (float*)(sm + 16896);   // 256
    uint32_t aring = (uint32_t)__cvta_generic_to_shared(Asm);
    uint32_t bring = (uint32_t)__cvta_generic_to_shared(Bsm);

    const int tid = threadIdx.x, lane = tid & 31, wid = tid >> 5;
    const int e = blockIdx.y, bx = blockIdx.x, rb = bx * 64;
    const int mt = wid & 3, ntg = (wid >> 2) * 8;
    const int g = lane >> 2, tig = lane & 3;
    const int nh = wid >> 2;

    if (tid < 128) {
        b1s[tid] = eb1[e * H_ + tid];
        b2s[tid] = eb2[e * H_ + tid];
        w3s[tid] = ew3[e * H_ * L_ + tid];
        w3s[tid + 128] = ew3[e * H_ * L_ + 128 + tid];
    }

    const uint32_t* xb  = Xp + (size_t)(bx >> 1) * 16 * 2048;
    const uint32_t* w1b = Wp + EW1_OFF + (size_t)e * 32768;
    const uint32_t* w2b = Wp + EW2_OFF + (size_t)e * 8192;

    float acc[8][4];
#pragma unroll
    for (int j = 0; j < 8; j++)
#pragma unroll
        for (int q = 0; q < 4; q++) acc[j][q] = 0.f;

    // ---- GEMM1: x[64,512] @ w1, pipelined ----
    gemm_pipe64(aring, bring, xb, bx & 1, w1b, Asm, Bsm, 16, acc, mt, ntg, lane, tid);

    __syncthreads();

    // issue all 4 w2 chunks into the B ring, overlapping epilogue1
#pragma unroll
    for (int c = 0; c < 4; c++)
        issue_chunk(bring + c * 8192, w2b + c * 2048, tid);
    CP_COMMIT();

    // ---- epilogue1: h1 = relu(acc + b1) -> H1 ----
#pragma unroll
    for (int j = 0; j < 8; j++) {
        int nl = nh * 64 + j * 8 + 2 * tig;
        float v00 = fmaxf(acc[j][0] + b1s[nl], 0.f);
        float v01 = fmaxf(acc[j][1] + b1s[nl + 1], 0.f);
        float v10 = fmaxf(acc[j][2] + b1s[nl], 0.f);
        float v11 = fmaxf(acc[j][3] + b1s[nl + 1], 0.f);
        int r0 = mt * 16 + g, r1 = r0 + 8;
        int ch = nl >> 5, kp = (nl & 31) >> 1;
        H1[ch * 1024 + afrag64(r0, kp)] = pack_h2(v00, v01);
        H1[ch * 1024 + afrag64(r1, kp)] = pack_h2(v10, v11);
    }

#pragma unroll
    for (int j = 0; j < 8; j++)
#pragma unroll
        for (int q = 0; q < 4; q++) acc[j][q] = 0.f;

    CP_WAIT0();
    __syncthreads();

    // ---- GEMM2: h1[64,128] @ w2, 4 chunks ----
#pragma unroll
    for (int c = 0; c < 4; c++)
        compute_bk64(H1 + c * 1024, Bsm + c * 2048, acc, mt, ntg, lane);

    // ---- epilogue2 + GEMM3 ----
    {
        float zp[2][2];
        zp[0][0] = zp[0][1] = zp[1][0] = zp[1][1] = 0.f;
#pragma unroll
        for (int j = 0; j < 8; j++) {
            int nl0 = nh * 64 + j * 8 + 2 * tig, nl1 = nl0 + 1;
            float h00 = fmaxf(acc[j][0] + b2s[nl0], 0.f);
            float h01 = fmaxf(acc[j][1] + b2s[nl1], 0.f);
            float h10 = fmaxf(acc[j][2] + b2s[nl0], 0.f);
            float h11 = fmaxf(acc[j][3] + b2s[nl1], 0.f);
            float w00 = w3s[nl0 * 2], w01 = w3s[nl0 * 2 + 1];
            float w10 = w3s[nl1 * 2], w11 = w3s[nl1 * 2 + 1];
            zp[0][0] += h00 * w00 + h01 * w10;
            zp[0][1] += h00 * w01 + h01 * w11;
            zp[1][0] += h10 * w00 + h11 * w10;
            zp[1][1] += h10 * w01 + h11 * w11;
        }
#pragma unroll
        for (int h = 0; h < 2; h++)
#pragma unroll
            for (int l = 0; l < 2; l++) {
                zp[h][l] += __shfl_xor_sync(0xFFFFFFFFu, zp[h][l], 1);
                zp[h][l] += __shfl_xor_sync(0xFFFFFFFFu, zp[h][l], 2);
            }
        if (tig == 0) {
#pragma unroll
            for (int h = 0; h < 2; h++) {
                int row = mt * 16 + h * 8 + g;
                zbuf[(nh * 64 + row) * 2]     = zp[h][0];
                zbuf[(nh * 64 + row) * 2 + 1] = zp[h][1];
            }
        }
        __syncthreads();
        if (tid < 64) {
            float s0 = zbuf[tid * 2]     + zbuf[(64 + tid) * 2]     + eb3[e * 2];
            float s1 = zbuf[tid * 2 + 1] + zbuf[(64 + tid) * 2 + 1] + eb3[e * 2 + 1];
            *(float2*)&chart[((size_t)e * B_ + rb + tid) * 2] = make_float2(s0, s1);
        }
    }
}

__global__ __launch_bounds__(256)
void z_combine(const float* __restrict__ weights, const float* __restrict__ chart,
               float* __restrict__ z) {
    int idx = blockIdx.x * blockDim.x + threadIdx.x;
    int b = idx >> 1, l = idx & 1;
    float s = 0.f;
#pragma unroll
    for (int e = 0; e < E_; e++)
        s += weights[(size_t)b * E_ + e] * chart[((size_t)e * B_ + b) * L_ + l];
    z[idx] = s;
}

// ---------------------------------------------------------------------------
extern "C" void kernel_launch(void* const* d_in, const int* in_sizes, int n_in,
                              void* d_out, int out_size) {
    const float* x   = (const float*)d_in[0];
    const float* u   = (const float*)d_in[1];
    const float* rw1 = (const float*)d_in[2];
    const float* rb1 = (const float*)d_in[3];
    const float* rw2 = (const float*)d_in[4];
    const float* rb2 = (const float*)d_in[5];
    const float* rw3 = (const float*)d_in[6];
    const float* rb3 = (const float*)d_in[7];
    const float* ew1 = (const float*)d_in[8];
    const float* eb1 = (const float*)d_in[9];
    const float* ew2 = (const float*)d_in[10];
    const float* eb2 = (const float*)d_in[11];
    const float* ew3 = (const float*)d_in[12];
    const float* eb3 = (const float*)d_in[13];

    float* out     = (float*)d_out;
    float* z       = out;
    float* weights = out + (size_t)B_ * L_;
    float* chart   = weights + (size_t)B_ * E_;

    uint32_t *Xp, *Wf, *R1f;
    cudaGetSymbolAddress((void**)&Xp,  g_Xp);
    cudaGetSymbolAddress((void**)&Wf,  g_Wf);
    cudaGetSymbolAddress((void**)&R1f, g_R1f);

    const int R1_SMEM  = 16512 * 4;   // ~66 KB
    const int R23_SMEM = 14992 * 4;   // ~60 KB
    const int EX_SMEM  = 17152 * 4;   // ~69 KB
    cudaFuncSetAttribute(router1_f16,  cudaFuncAttributeMaxDynamicSharedMemorySize, R1_SMEM);
    cudaFuncSetAttribute(router23_f16, cudaFuncAttributeMaxDynamicSharedMemorySize, R23_SMEM);
    cudaFuncSetAttribute(expert_f16,   cudaFuncAttributeMaxDynamicSharedMemorySize, EX_SMEM);

    prep_x<<<4096, 256>>>(x, Xp);
    prep_w<<<1920, 256>>>(rw1, rw2, ew1, ew2, Wf);
    router1_f16<<<dim3(256, 2), 256, R1_SMEM>>>(Xp, Wf + RW1_OFF, rb1, R1f);
    router23_f16<<<512, 256, R23_SMEM>>>(R1f, Wf + RW2_OFF, rb2, rw3, rb3, u, weights);
    expert_f16<<<dim3(512, E_), 256, EX_SMEM>>>(Xp, Wf, eb1, eb2, ew3, eb3, chart);
    z_combine<<<(B_ * L_) / 256, 256>>>(weights, chart, z);
}

// round 9
// speedup vs baseline: 1.2203x; 1.2203x over previous
#include <cuda_runtime.h>
#include <cstdint>

#define B_   32768
#define D_   512
#define E_   10
#define H_   128
#define L_   2
#define RH1_ 256
#define RH2_ 128

__device__ uint32_t g_Xp[8388608];    // x, A-fragment fp16: 256 tiles x 16 ch x 2048
__device__ uint32_t g_Wf[491520];     // weights, B-fragment fp16
__device__ uint32_t g_R1f[4194304];   // router h1, A-fragment fp16: 256 tiles x 8 ch

#define RW1_OFF 0
#define RW2_OFF 65536
#define EW1_OFF 81920
#define EW2_OFF 409600

#define MMA_F16(d, a, bb0, bb1) \
    asm volatile("mma.sync.aligned.m16n8k16.row.col.f32.f16.f16.f32 " \
        "{%0,%1,%2,%3},{%4,%5,%6,%7},{%8,%9},{%0,%1,%2,%3};" \
        : "+f"((d)[0]), "+f"((d)[1]), "+f"((d)[2]), "+f"((d)[3]) \
        : "r"((a).x), "r"((a).y), "r"((a).z), "r"((a).w), "r"(bb0), "r"(bb1))

static __device__ __forceinline__ uint32_t pack_h2(float lo, float hi) {
    uint32_t r;
    asm("cvt.rn.f16x2.f32 %0, %1, %2;" : "=r"(r) : "f"(hi), "f"(lo));
    return r;
}

// fragment slot (u32) for (row, kpair) in a 128-row A chunk
static __device__ __forceinline__ int afrag_off(int row, int kp) {
    int ks = kp >> 3, tig = kp & 3, bh = (kp & 7) >> 2;
    int mt = row >> 4, r16 = row & 15, g = r16 & 7, hi = r16 >> 3;
    return (ks * 8 + mt) * 128 + ((g * 4 + tig) << 2) + hi + 2 * bh;
}

// ---- cp.async --------------------------------------------------------------
static __device__ __forceinline__ void cpasync16(uint32_t saddr, const void* g) {
    asm volatile("cp.async.cg.shared.global [%0], [%1], 16;" :: "r"(saddr), "l"(g));
}
#define CP_COMMIT() asm volatile("cp.async.commit_group;" ::: "memory")
#define CP_WAIT2()  asm volatile("cp.async.wait_group 2;" ::: "memory")
#define CP_WAIT0()  asm volatile("cp.async.wait_group 0;" ::: "memory")

static __device__ __forceinline__ void issue_chunk(uint32_t sbase, const uint32_t* g,
                                                   int tid) {
    cpasync16(sbase + tid * 16, g + tid * 4);
    cpasync16(sbase + 4096 + tid * 16, g + (tid + 256) * 4);
}

// One BK=32 chunk: 2 k16 steps, warp tile 32x64 -> 32 MMAs
static __device__ __forceinline__ void compute_bk(const uint32_t* As, const uint32_t* Bs,
                                                  float (*acc)[8][4],
                                                  int mtg, int ntg, int lane) {
#pragma unroll
    for (int ks = 0; ks < 2; ks++) {
        uint2 b[8];
#pragma unroll
        for (int j = 0; j < 8; j++)
            b[j] = *(const uint2*)&Bs[(ks * 16 + ntg + j) * 64 + lane * 2];
        uint4 a[2];
#pragma unroll
        for (int i = 0; i < 2; i++)
            a[i] = *(const uint4*)&As[(ks * 8 + mtg + i) * 128 + lane * 4];
#pragma unroll
        for (int i = 0; i < 2; i++)
#pragma unroll
            for (int j = 0; j < 8; j++)
                MMA_F16(acc[i][j], a[i], b[j].x, b[j].y);
    }
}

// Pipelined mainloop over nch chunks (ring of 4 stages).
static __device__ __forceinline__ void gemm_pipe(uint32_t aring, uint32_t bring,
                                                 const uint32_t* gA, const uint32_t* gB,
                                                 const uint32_t* Asm, const uint32_t* Bsm,
                                                 int nch, float (*acc)[8][4],
                                                 int mtg, int ntg, int lane, int tid) {
#pragma unroll
    for (int s = 0; s < 3; s++) {
        issue_chunk(aring + s * 8192, gA + s * 2048, tid);
        issue_chunk(bring + s * 8192, gB + s * 2048, tid);
        CP_COMMIT();
    }
#pragma unroll 1
    for (int c = 0; c < nch; c++) {
        CP_WAIT2();
        __syncthreads();
        if (c + 3 < nch) {
            int st = (c + 3) & 3;
            issue_chunk(aring + st * 8192, gA + (c + 3) * 2048, tid);
            issue_chunk(bring + st * 8192, gB + (c + 3) * 2048, tid);
        }
        CP_COMMIT();
        compute_bk(Asm + (c & 3) * 2048, Bsm + (c & 3) * 2048, acc, mtg, ntg, lane);
    }
}

// ---- prep: x -> A-fragment fp16 (smem staged, coalesced reads) -------------
__global__ __launch_bounds__(256)
void prep_x(const float* __restrict__ x, uint32_t* __restrict__ xp) {
    __shared__ float tile[128][33];
    const int tid = threadIdx.x;
    const int rt = blockIdx.x >> 4, c = blockIdx.x & 15;
#pragma unroll
    for (int t = 0; t < 4; t++) {
        int idx = tid + t * 256;
        int row = idx >> 3, q = (idx & 7) * 4;
        float4 v = *(const float4*)&x[(size_t)(rt * 128 + row) * D_ + c * 32 + q];
        tile[row][q] = v.x; tile[row][q + 1] = v.y;
        tile[row][q + 2] = v.z; tile[row][q + 3] = v.w;
    }
    __syncthreads();
    uint32_t* dst = xp + ((size_t)rt * 16 + c) * 2048 + tid * 8;
    uint32_t r8[8];
#pragma unroll
    for (int j = 0; j < 8; j++) {
        int w = tid * 8 + j;
        int slot = w >> 7, ks = slot >> 3, mt = slot & 7;
        int within = w & 127, lane = within >> 2, r = within & 3;
        int g = lane >> 2, tig = lane & 3, hi = r & 1, bh = r >> 1;
        int row = mt * 16 + hi * 8 + g;
        int k = (ks * 8 + bh * 4 + tig) * 2;
        r8[j] = pack_h2(tile[row][k], tile[row][k + 1]);
    }
    *(uint4*)dst       = make_uint4(r8[0], r8[1], r8[2], r8[3]);
    *(uint4*)(dst + 4) = make_uint4(r8[4], r8[5], r8[6], r8[7]);
}

// ---- prep: all weights -> B-fragment fp16 ---------------------------------
__global__ __launch_bounds__(256)
void prep_w(const float* __restrict__ rw1, const float* __restrict__ rw2,
            const float* __restrict__ ew1, const float* __restrict__ ew2,
            uint32_t* __restrict__ wp) {
    int id = blockIdx.x * 256 + threadIdx.x;
    int w = id & 2047;
    int slot = w >> 6, ks = slot >> 4, nt = slot & 15;
    int within = w & 63, lane = within >> 1, r = within & 1;
    int g = lane >> 2, tig = lane & 3;
    int nl = nt * 8 + g;
    int kk = ks * 16 + (r * 4 + tig) * 2;
    float v0, v1;
    if (id < 65536) {
        int ch = id >> 11, nb = ch >> 4, c = ch & 15;
        int n = nb * 128 + nl, k = c * 32 + kk;
        v0 = rw1[k * RH1_ + n]; v1 = rw1[(k + 1) * RH1_ + n];
    } else if (id < 81920) {
        int c = (id - 65536) >> 11, k = c * 32 + kk;
        v0 = rw2[k * RH2_ + nl]; v1 = rw2[(k + 1) * RH2_ + nl];
    } else if (id < 409600) {
        int t = id - 81920, e = t >> 15, c = (t >> 11) & 15, k = c * 32 + kk;
        v0 = ew1[(size_t)e * 65536 + k * H_ + nl];
        v1 = ew1[(size_t)e * 65536 + (k + 1) * H_ + nl];
    } else {
        int t = id - 409600, e = t >> 13, c = (t >> 11) & 3, k = c * 32 + kk;
        v0 = ew2[(size_t)e * 16384 + k * H_ + nl];
        v1 = ew2[(size_t)e * 16384 + (k + 1) * H_ + nl];
    }
    wp[id] = pack_h2(v0, v1);
}

// ---- router GEMM1: Xp @ rw1 -> R1f (A-fragment fp16), bias+relu ------------
__global__ __launch_bounds__(256)
void router1_f16(const uint32_t* __restrict__ Xp, const uint32_t* __restrict__ Wp,
                 const float* __restrict__ rb1, uint32_t* __restrict__ R1f) {
    extern __shared__ uint32_t sm[];
    uint32_t* Asm = sm;
    uint32_t* Bsm = sm + 8192;
    float* bs = (float*)(sm + 16384);
    uint32_t aring = (uint32_t)__cvta_generic_to_shared(Asm);
    uint32_t bring = (uint32_t)__cvta_generic_to_shared(Bsm);

    const int tid = threadIdx.x, lane = tid & 31, wid = tid >> 5;
    const int bx = blockIdx.x, nb = blockIdx.y, cb = nb * 128;
    const int mtg = (wid & 3) * 2, ntg = (wid >> 2) * 8;
    if (tid < 128) bs[tid] = rb1[cb + tid];

    float acc[2][8][4];
#pragma unroll
    for (int i = 0; i < 2; i++)
#pragma unroll
        for (int j = 0; j < 8; j++)
#pragma unroll
            for (int q = 0; q < 4; q++) acc[i][j][q] = 0.f;

    gemm_pipe(aring, bring, Xp + (size_t)bx * 16 * 2048,
              Wp + (size_t)nb * 16 * 2048, Asm, Bsm, 16, acc, mtg, ntg, lane, tid);

    const int g = lane >> 2, tig = lane & 3;
    const int mrow = (wid & 3) * 32, nh = wid >> 2;
#pragma unroll
    for (int i = 0; i < 2; i++)
#pragma unroll
        for (int j = 0; j < 8; j++) {
            int nl = nh * 64 + j * 8 + 2 * tig;
            float b0 = bs[nl], b1 = bs[nl + 1];
            float v00 = fmaxf(acc[i][j][0] + b0, 0.f);
            float v01 = fmaxf(acc[i][j][1] + b1, 0.f);
            float v10 = fmaxf(acc[i][j][2] + b0, 0.f);
            float v11 = fmaxf(acc[i][j][3] + b1, 0.f);
            int r0 = mrow + i * 16 + g, r1 = r0 + 8;
            int n = cb + nl;
            int ch = n >> 5, kp = (n & 31) >> 1;
            size_t base = ((size_t)bx * 8 + ch) * 2048;
            R1f[base + afrag_off(r0, kp)] = pack_h2(v00, v01);
            R1f[base + afrag_off(r1, kp)] = pack_h2(v10, v11);
        }
}

// ---- router GEMM2 + logits + gumbel softmax -> weights ---------------------
__global__ __launch_bounds__(256)
void router23_f16(const uint32_t* __restrict__ R1f, const uint32_t* __restrict__ Wp,
                  const float* __restrict__ rb2, const float* __restrict__ rw3,
                  const float* __restrict__ rb3, const float* __restrict__ u,
                  float* __restrict__ weights) {
    extern __shared__ uint32_t sm[];
    uint32_t* Asm = sm;
    uint32_t* Bsm = sm + 8192;
    float* bs  = (float*)(sm + 16384);   // 128
    float* b3  = (float*)(sm + 16512);   // 16
    float* w3s = (float*)(sm + 16528);   // 1280
    float* zbuf = (float*)(sm + 17808);  // 2560
    uint32_t aring = (uint32_t)__cvta_generic_to_shared(Asm);
    uint32_t bring = (uint32_t)__cvta_generic_to_shared(Bsm);

    const int tid = threadIdx.x, lane = tid & 31, wid = tid >> 5;
    const int bx = blockIdx.x, rb = bx * 128;
    const int mtg = (wid & 3) * 2, ntg = (wid >> 2) * 8;
    if (tid < 128) bs[tid] = rb2[tid];
    if (tid < E_)  b3[tid] = rb3[tid];
    for (int i = tid; i < RH2_ * E_; i += 256) w3s[i] = rw3[i];

    float acc[2][8][4];
#pragma unroll
    for (int i = 0; i < 2; i++)
#pragma unroll
        for (int j = 0; j < 8; j++)
#pragma unroll
            for (int q = 0; q < 4; q++) acc[i][j][q] = 0.f;

    gemm_pipe(aring, bring, R1f + (size_t)bx * 8 * 2048,
              Wp, Asm, Bsm, 8, acc, mtg, ntg, lane, tid);

    const int g = lane >> 2, tig = lane & 3;
    const int mrow = (wid & 3) * 32, nh = wid >> 2;
    float zp[2][2][E_];
#pragma unroll
    for (int i = 0; i < 2; i++)
#pragma unroll
        for (int h = 0; h < 2; h++)
#pragma unroll
            for (int e = 0; e < E_; e++) zp[i][h][e] = 0.f;

#pragma unroll
    for (int j = 0; j < 8; j++) {
        int nl0 = nh * 64 + j * 8 + 2 * tig, nl1 = nl0 + 1;
        float wA[E_], wB[E_];
#pragma unroll
        for (int e = 0; e < E_; e++) { wA[e] = w3s[nl0 * E_ + e]; wB[e] = w3s[nl1 * E_ + e]; }
#pragma unroll
        for (int i = 0; i < 2; i++) {
            float v00 = fmaxf(acc[i][j][0] + bs[nl0], 0.f);
            float v01 = fmaxf(acc[i][j][1] + bs[nl1], 0.f);
            float v10 = fmaxf(acc[i][j][2] + bs[nl0], 0.f);
            float v11 = fmaxf(acc[i][j][3] + bs[nl1], 0.f);
#pragma unroll
            for (int e = 0; e < E_; e++) {
                zp[i][0][e] += v00 * wA[e] + v01 * wB[e];
                zp[i][1][e] += v10 * wA[e] + v11 * wB[e];
            }
        }
    }
#pragma unroll
    for (int i = 0; i < 2; i++)
#pragma unroll
        for (int h = 0; h < 2; h++)
#pragma unroll
            for (int e = 0; e < E_; e++) {
                zp[i][h][e] += __shfl_xor_sync(0xFFFFFFFFu, zp[i][h][e], 1);
                zp[i][h][e] += __shfl_xor_sync(0xFFFFFFFFu, zp[i][h][e], 2);
            }
    if (tig == 0) {
#pragma unroll
        for (int i = 0; i < 2; i++)
#pragma unroll
            for (int h = 0; h < 2; h++) {
                int row = mrow + i * 16 + h * 8 + g;
#pragma unroll
                for (int e = 0; e < E_; e++)
                    zbuf[(nh * 128 + row) * E_ + e] = zp[i][h][e];
            }
    }
    __syncthreads();
    if (tid < 128) {
        int b = rb + tid;
        float lg[E_], mx = -1e30f;
#pragma unroll
        for (int e = 0; e < E_; e++) {
            float uu = u[(size_t)b * E_ + e];
            uu = fminf(fmaxf(uu, 1e-10f), 1.0f);
            float gg = -logf(-logf(uu) + 1e-10f);
            lg[e] = (zbuf[tid * E_ + e] + zbuf[(128 + tid) * E_ + e] + b3[e] + gg)
                    * (1.0f / 3.0f);
            mx = fmaxf(mx, lg[e]);
        }
        float sum = 0.f;
#pragma unroll
        for (int e = 0; e < E_; e++) { lg[e] = expf(lg[e] - mx); sum += lg[e]; }
        float inv = 1.f / sum;
#pragma unroll
        for (int e = 0; e < E_; e++) weights[(size_t)b * E_ + e] = lg[e] * inv;
    }
}

// ---- fused expert chain (pipelined, BM=128) --------------------------------
__global__ __launch_bounds__(256)
void expert_f16(const uint32_t* __restrict__ Xp, const uint32_t* __restrict__ Wp,
                const float* __restrict__ eb1, const float* __restrict__ eb2,
                const float* __restrict__ ew3, const float* __restrict__ eb3,
                float* __restrict__ chart) {
    extern __shared__ uint32_t sm[];
    uint32_t* Asm = sm;                 // 4 x 2048
    uint32_t* Bsm = sm + 8192;          // 4 x 2048
    uint32_t* H1  = sm + 16384;         // 4 x 2048 (h1, A-fragment fp16)
    float* b1s  = (float*)(sm + 24576);
    float* b2s  = (float*)(sm + 24704);
    float* w3s  = (float*)(sm + 24832);
    float* zbuf = (float*)(sm + 25088);
    uint32_t aring = (uint32_t)__cvta_generic_to_shared(Asm);
    uint32_t bring = (uint32_t)__cvta_generic_to_shared(Bsm);

    const int tid = threadIdx.x, lane = tid & 31, wid = tid >> 5;
    const int e = blockIdx.y, bx = blockIdx.x, rb = bx * 128;
    const int mtg = (wid & 3) * 2, ntg = (wid >> 2) * 8;
    const int g = lane >> 2, tig = lane & 3;
    const int mrow = (wid & 3) * 32, nh = wid >> 2;

    if (tid < 128) {
        b1s[tid] = eb1[e * H_ + tid];
        b2s[tid] = eb2[e * H_ + tid];
        w3s[tid] = ew3[e * H_ * L_ + tid];
        w3s[tid + 128] = ew3[e * H_ * L_ + 128 + tid];
    }

    const uint32_t* xb  = Xp + (size_t)bx * 16 * 2048;
    const uint32_t* w1b = Wp + EW1_OFF + (size_t)e * 32768;
    const uint32_t* w2b = Wp + EW2_OFF + (size_t)e * 8192;

    float acc[2][8][4];
#pragma unroll
    for (int i = 0; i < 2; i++)
#pragma unroll
        for (int j = 0; j < 8; j++)
#pragma unroll
            for (int q = 0; q < 4; q++) acc[i][j][q] = 0.f;

    gemm_pipe(aring, bring, xb, w1b, Asm, Bsm, 16, acc, mtg, ntg, lane, tid);

    __syncthreads();

#pragma unroll
    for (int c = 0; c < 4; c++)
        issue_chunk(bring + c * 8192, w2b + c * 2048, tid);
    CP_COMMIT();

#pragma unroll
    for (int i = 0; i < 2; i++)
#pragma unroll
        for (int j = 0; j < 8; j++) {
            int nl = nh * 64 + j * 8 + 2 * tig;
            float v00 = fmaxf(acc[i][j][0] + b1s[nl], 0.f);
            float v01 = fmaxf(acc[i][j][1] + b1s[nl + 1], 0.f);
            float v10 = fmaxf(acc[i][j][2] + b1s[nl], 0.f);
            float v11 = fmaxf(acc[i][j][3] + b1s[nl + 1], 0.f);
            int r0 = mrow + i * 16 + g, r1 = r0 + 8;
            int ch = nl >> 5, kp = (nl & 31) >> 1;
            H1[ch * 2048 + afrag_off(r0, kp)] = pack_h2(v00, v01);
            H1[ch * 2048 + afrag_off(r1, kp)] = pack_h2(v10, v11);
        }

#pragma unroll
    for (int i = 0; i < 2; i++)
#pragma unroll
        for (int j = 0; j < 8; j++)
#pragma unroll
            for (int q = 0; q < 4; q++) acc[i][j][q] = 0.f;

    CP_WAIT0();
    __syncthreads();

#pragma unroll
    for (int c = 0; c < 4; c++)
        compute_bk(H1 + c * 2048, Bsm + c * 2048, acc, mtg, ntg, lane);

    {
        float zp[2][2][2];
#pragma unroll
        for (int i = 0; i < 2; i++)
#pragma unroll
            for (int h = 0; h < 2; h++) { zp[i][h][0] = 0.f; zp[i][h][1] = 0.f; }
#pragma unroll
        for (int i = 0; i < 2; i++)
#pragma unroll
            for (int j = 0; j < 8; j++) {
                int nl0 = nh * 64 + j * 8 + 2 * tig, nl1 = nl0 + 1;
                float h00 = fmaxf(acc[i][j][0] + b2s[nl0], 0.f);
                float h01 = fmaxf(acc[i][j][1] + b2s[nl1], 0.f);
                float h10 = fmaxf(acc[i][j][2] + b2s[nl0], 0.f);
                float h11 = fmaxf(acc[i][j][3] + b2s[nl1], 0.f);
                float w00 = w3s[nl0 * 2], w01 = w3s[nl0 * 2 + 1];
                float w10 = w3s[nl1 * 2], w11 = w3s[nl1 * 2 + 1];
                zp[i][0][0] += h00 * w00 + h01 * w10;
                zp[i][0][1] += h00 * w01 + h01 * w11;
                zp[i][1][0] += h10 * w00 + h11 * w10;
                zp[i][1][1] += h10 * w01 + h11 * w11;
            }
#pragma unroll
        for (int i = 0; i < 2; i++)
#pragma unroll
            for (int h = 0; h < 2; h++)
#pragma unroll
                for (int l = 0; l < 2; l++) {
                    zp[i][h][l] += __shfl_xor_sync(0xFFFFFFFFu, zp[i][h][l], 1);
                    zp[i][h][l] += __shfl_xor_sync(0xFFFFFFFFu, zp[i][h][l], 2);
                }
        if (tig == 0) {
#pragma unroll
            for (int i = 0; i < 2; i++)
#pragma unroll
                for (int h = 0; h < 2; h++) {
                    int row = mrow + i * 16 + h * 8 + g;
                    zbuf[(nh * 128 + row) * 2]     = zp[i][h][0];
                    zbuf[(nh * 128 + row) * 2 + 1] = zp[i][h][1];
                }
        }
        __syncthreads();
        if (tid < 128) {
            float s0 = zbuf[tid * 2]     + zbuf[(128 + tid) * 2]     + eb3[e * 2];
            float s1 = zbuf[tid * 2 + 1] + zbuf[(128 + tid) * 2 + 1] + eb3[e * 2 + 1];
            *(float2*)&chart[((size_t)e * B_ + rb + tid) * 2] = make_float2(s0, s1);
        }
    }
}

__global__ __launch_bounds__(256)
void z_combine(const float* __restrict__ weights, const float* __restrict__ chart,
               float* __restrict__ z) {
    int idx = blockIdx.x * blockDim.x + threadIdx.x;
    int b = idx >> 1, l = idx & 1;
    float s = 0.f;
#pragma unroll
    for (int e = 0; e < E_; e++)
        s += weights[(size_t)b * E_ + e] * chart[((size_t)e * B_ + b) * L_ + l];
    z[idx] = s;
}

// ---------------------------------------------------------------------------
extern "C" void kernel_launch(void* const* d_in, const int* in_sizes, int n_in,
                              void* d_out, int out_size) {
    const float* x   = (const float*)d_in[0];
    const float* u   = (const float*)d_in[1];
    const float* rw1 = (const float*)d_in[2];
    const float* rb1 = (const float*)d_in[3];
    const float* rw2 = (const float*)d_in[4];
    const float* rb2 = (const float*)d_in[5];
    const float* rw3 = (const float*)d_in[6];
    const float* rb3 = (const float*)d_in[7];
    const float* ew1 = (const float*)d_in[8];
    const float* eb1 = (const float*)d_in[9];
    const float* ew2 = (const float*)d_in[10];
    const float* eb2 = (const float*)d_in[11];
    const float* ew3 = (const float*)d_in[12];
    const float* eb3 = (const float*)d_in[13];

    float* out     = (float*)d_out;
    float* z       = out;
    float* weights = out + (size_t)B_ * L_;
    float* chart   = weights + (size_t)B_ * E_;

    uint32_t *Xp, *Wf, *R1f;
    cudaGetSymbolAddress((void**)&Xp,  g_Xp);
    cudaGetSymbolAddress((void**)&Wf,  g_Wf);
    cudaGetSymbolAddress((void**)&R1f, g_R1f);

    const int R1_SMEM = 16512 * 4;   // ~66 KB
    const int R2_SMEM = 20368 * 4;   // ~81 KB
    const int EX_SMEM = 25600 * 4;   // 100 KB
    cudaFuncSetAttribute(router1_f16,  cudaFuncAttributeMaxDynamicSharedMemorySize, R1_SMEM);
    cudaFuncSetAttribute(router23_f16, cudaFuncAttributeMaxDynamicSharedMemorySize, R2_SMEM);
    cudaFuncSetAttribute(expert_f16,   cudaFuncAttributeMaxDynamicSharedMemorySize, EX_SMEM);

    // Side stream + events for graph-captured fork/join (created once, host-side).
    static cudaStream_t s2 = nullptr;
    static cudaEvent_t evFork = nullptr, evJoin = nullptr;
    if (s2 == nullptr) {
        cudaStreamCreateWithFlags(&s2, cudaStreamNonBlocking);
        cudaEventCreateWithFlags(&evFork, cudaEventDisableTiming);
        cudaEventCreateWithFlags(&evJoin, cudaEventDisableTiming);
    }

    prep_x<<<4096, 256>>>(x, Xp);
    prep_w<<<1920, 256>>>(rw1, rw2, ew1, ew2, Wf);

    // Fork: router chain on s2, expert on main stream (independent work).
    cudaEventRecord(evFork, 0);
    cudaStreamWaitEvent(s2, evFork, 0);
    router1_f16<<<dim3(256, 2), 256, R1_SMEM, s2>>>(Xp, Wf + RW1_OFF, rb1, R1f);
    router23_f16<<<256, 256, R2_SMEM, s2>>>(R1f, Wf + RW2_OFF, rb2, rw3, rb3, u, weights);
    cudaEventRecord(evJoin, s2);

    expert_f16<<<dim3(256, E_), 256, EX_SMEM>>>(Xp, Wf, eb1, eb2, ew3, eb3, chart);

    // Join: z_combine needs both weights (s2) and chart (main).
    cudaStreamWaitEvent(0, evJoin, 0);
    z_combine<<<(B_ * L_) / 256, 256>>>(weights, chart, z);
}

// round 13
// speedup vs baseline: 1.2893x; 1.0565x over previous
#include <cuda_runtime.h>
#include <cstdint>

#define B_   32768
#define D_   512
#define E_   10
#define H_   128
#define L_   2
#define RH1_ 256
#define RH2_ 128

__device__ uint32_t g_Xp[8388608];    // x, A-fragment fp16: 256 tiles x 16 ch x 2048
__device__ uint32_t g_Wf[491520];     // weights, B-fragment fp16
__device__ uint32_t g_R1f[4194304];   // router h1, A-fragment fp16: 256 tiles x 8 ch

#define RW1_OFF 0
#define RW2_OFF 65536
#define EW1_OFF 81920
#define EW2_OFF 409600

#define MMA_F16(d, a, bb0, bb1) \
    asm volatile("mma.sync.aligned.m16n8k16.row.col.f32.f16.f16.f32 " \
        "{%0,%1,%2,%3},{%4,%5,%6,%7},{%8,%9},{%0,%1,%2,%3};" \
        : "+f"((d)[0]), "+f"((d)[1]), "+f"((d)[2]), "+f"((d)[3]) \
        : "r"((a).x), "r"((a).y), "r"((a).z), "r"((a).w), "r"(bb0), "r"(bb1))

static __device__ __forceinline__ uint32_t pack_h2(float lo, float hi) {
    uint32_t r;
    asm("cvt.rn.f16x2.f32 %0, %1, %2;" : "=r"(r) : "f"(hi), "f"(lo));
    return r;
}

// fragment slot (u32) for (row, kpair) in a 128-row A chunk
static __device__ __forceinline__ int afrag_off(int row, int kp) {
    int ks = kp >> 3, tig = kp & 3, bh = (kp & 7) >> 2;
    int mt = row >> 4, r16 = row & 15, g = r16 & 7, hi = r16 >> 3;
    return (ks * 8 + mt) * 128 + ((g * 4 + tig) << 2) + hi + 2 * bh;
}

// ---- cp.async --------------------------------------------------------------
static __device__ __forceinline__ void cpasync16(uint32_t saddr, const void* g) {
    asm volatile("cp.async.cg.shared.global [%0], [%1], 16;" :: "r"(saddr), "l"(g));
}
#define CP_COMMIT() asm volatile("cp.async.commit_group;" ::: "memory")
#define CP_WAIT1()  asm volatile("cp.async.wait_group 1;" ::: "memory")
#define CP_WAIT0()  asm volatile("cp.async.wait_group 0;" ::: "memory")

// one 2048-u32 chunk (8 KB)
static __device__ __forceinline__ void issue_chunk(uint32_t sbase, const uint32_t* g,
                                                   int tid) {
    cpasync16(sbase + tid * 16, g + tid * 4);
    cpasync16(sbase + 4096 + tid * 16, g + (tid + 256) * 4);
}
// one group = 2 A chunks (16 KB) + 2 B chunks (16 KB); A at sbase, B at +16384 B
static __device__ __forceinline__ void issue_pair(uint32_t sbase, const uint32_t* gA,
                                                  const uint32_t* gB, int tid) {
#pragma unroll
    for (int t = 0; t < 4; t++)
        cpasync16(sbase + (tid + t * 256) * 16, gA + (tid + t * 256) * 4);
#pragma unroll
    for (int t = 0; t < 4; t++)
        cpasync16(sbase + 16384 + (tid + t * 256) * 16, gB + (tid + t * 256) * 4);
}

// One BK=32 chunk: 2 k16 steps, warp tile 32x64 -> 32 MMAs
static __device__ __forceinline__ void compute_bk(const uint32_t* As, const uint32_t* Bs,
                                                  float (*acc)[8][4],
                                                  int mtg, int ntg, int lane) {
#pragma unroll
    for (int ks = 0; ks < 2; ks++) {
        uint2 b[8];
#pragma unroll
        for (int j = 0; j < 8; j++)
            b[j] = *(const uint2*)&Bs[(ks * 16 + ntg + j) * 64 + lane * 2];
        uint4 a[2];
#pragma unroll
        for (int i = 0; i < 2; i++)
            a[i] = *(const uint4*)&As[(ks * 8 + mtg + i) * 128 + lane * 4];
#pragma unroll
        for (int i = 0; i < 2; i++)
#pragma unroll
            for (int j = 0; j < 8; j++)
                MMA_F16(acc[i][j], a[i], b[j].x, b[j].y);
    }
}

// Pipelined mainloop: groups of 2 chunks, ring of 3 groups (one sync per group).
static __device__ __forceinline__ void gemm_pipe2(uint32_t ring, const uint32_t* gA,
                                                  const uint32_t* gB,
                                                  const uint32_t* smR,
                                                  int npair, float (*acc)[8][4],
                                                  int mtg, int ntg, int lane, int tid) {
    issue_pair(ring, gA, gB, tid);
    CP_COMMIT();
    issue_pair(ring + 32768, gA + 4096, gB + 4096, tid);
    CP_COMMIT();
#pragma unroll 1
    for (int i = 0; i < npair; i++) {
        CP_WAIT1();
        __syncthreads();
        if (i + 2 < npair) {
            int s = (i + 2) % 3;
            issue_pair(ring + s * 32768, gA + (2 * i + 4) * 2048,
                       gB + (2 * i + 4) * 2048, tid);
        }
        CP_COMMIT();
        const uint32_t* base = smR + (i % 3) * 8192;
        compute_bk(base,        base + 4096, acc, mtg, ntg, lane);
        compute_bk(base + 2048, base + 6144, acc, mtg, ntg, lane);
    }
}

// ---- prep: x -> A-fragment fp16 AND weights -> B-fragment fp16 (one kernel) -
__global__ __launch_bounds__(256)
void prep_all(const float* __restrict__ x,
              const float* __restrict__ rw1, const float* __restrict__ rw2,
              const float* __restrict__ ew1, const float* __restrict__ ew2,
              uint32_t* __restrict__ xp, uint32_t* __restrict__ wp) {
    __shared__ float tile[128][33];
    const int tid = threadIdx.x;
    if (blockIdx.x < 1920) {
        int id = blockIdx.x * 256 + tid;
        int w = id & 2047;
        int slot = w >> 6, ks = slot >> 4, nt = slot & 15;
        int within = w & 63, lane = within >> 1, r = within & 1;
        int g = lane >> 2, tig = lane & 3;
        int nl = nt * 8 + g;
        int kk = ks * 16 + (r * 4 + tig) * 2;
        float v0, v1;
        if (id < 65536) {
            int ch = id >> 11, nb = ch >> 4, c = ch & 15;
            int n = nb * 128 + nl, k = c * 32 + kk;
            v0 = rw1[k * RH1_ + n]; v1 = rw1[(k + 1) * RH1_ + n];
        } else if (id < 81920) {
            int c = (id - 65536) >> 11, k = c * 32 + kk;
            v0 = rw2[k * RH2_ + nl]; v1 = rw2[(k + 1) * RH2_ + nl];
        } else if (id < 409600) {
            int t = id - 81920, e = t >> 15, c = (t >> 11) & 15, k = c * 32 + kk;
            v0 = ew1[(size_t)e * 65536 + k * H_ + nl];
            v1 = ew1[(size_t)e * 65536 + (k + 1) * H_ + nl];
        } else {
            int t = id - 409600, e = t >> 13, c = (t >> 11) & 3, k = c * 32 + kk;
            v0 = ew2[(size_t)e * 16384 + k * H_ + nl];
            v1 = ew2[(size_t)e * 16384 + (k + 1) * H_ + nl];
        }
        wp[id] = pack_h2(v0, v1);
    } else {
        int blk = blockIdx.x - 1920;
        const int rt = blk >> 4, c = blk & 15;
#pragma unroll
        for (int t = 0; t < 4; t++) {
            int idx = tid + t * 256;
            int row = idx >> 3, q = (idx & 7) * 4;
            float4 v = *(const float4*)&x[(size_t)(rt * 128 + row) * D_ + c * 32 + q];
            tile[row][q] = v.x; tile[row][q + 1] = v.y;
            tile[row][q + 2] = v.z; tile[row][q + 3] = v.w;
        }
        __syncthreads();
        uint32_t* dst = xp + ((size_t)rt * 16 + c) * 2048 + tid * 8;
        uint32_t r8[8];
#pragma unroll
        for (int j = 0; j < 8; j++) {
            int w = tid * 8 + j;
            int slot = w >> 7, ks = slot >> 3, mt = slot & 7;
            int within = w & 127, lane = within >> 2, r = within & 3;
            int g = lane >> 2, tig = lane & 3, hi = r & 1, bh = r >> 1;
            int row = mt * 16 + hi * 8 + g;
            int k = (ks * 8 + bh * 4 + tig) * 2;
            r8[j] = pack_h2(tile[row][k], tile[row][k + 1]);
        }
        *(uint4*)dst       = make_uint4(r8[0], r8[1], r8[2], r8[3]);
        *(uint4*)(dst + 4) = make_uint4(r8[4], r8[5], r8[6], r8[7]);
    }
}

// ---- router GEMM1: Xp @ rw1 -> R1f (A-fragment fp16), bias+relu ------------
__global__ __launch_bounds__(256)
void router1_f16(const uint32_t* __restrict__ Xp, const uint32_t* __restrict__ Wp,
                 const float* __restrict__ rb1, uint32_t* __restrict__ R1f) {
    extern __shared__ uint32_t sm[];
    float* bs = (float*)(sm + 24576);
    uint32_t ring = (uint32_t)__cvta_generic_to_shared(sm);

    const int tid = threadIdx.x, lane = tid & 31, wid = tid >> 5;
    const int bx = blockIdx.x, nb = blockIdx.y, cb = nb * 128;
    const int mtg = (wid & 3) * 2, ntg = (wid >> 2) * 8;
    if (tid < 128) bs[tid] = rb1[cb + tid];

    float acc[2][8][4];
#pragma unroll
    for (int i = 0; i < 2; i++)
#pragma unroll
        for (int j = 0; j < 8; j++)
#pragma unroll
            for (int q = 0; q < 4; q++) acc[i][j][q] = 0.f;

    gemm_pipe2(ring, Xp + (size_t)bx * 16 * 2048, Wp + (size_t)nb * 16 * 2048,
               sm, 8, acc, mtg, ntg, lane, tid);

    const int g = lane >> 2, tig = lane & 3;
    const int mrow = (wid & 3) * 32, nh = wid >> 2;
#pragma unroll
    for (int i = 0; i < 2; i++)
#pragma unroll
        for (int j = 0; j < 8; j++) {
            int nl = nh * 64 + j * 8 + 2 * tig;
            float b0 = bs[nl], b1 = bs[nl + 1];
            float v00 = fmaxf(acc[i][j][0] + b0, 0.f);
            float v01 = fmaxf(acc[i][j][1] + b1, 0.f);
            float v10 = fmaxf(acc[i][j][2] + b0, 0.f);
            float v11 = fmaxf(acc[i][j][3] + b1, 0.f);
            int r0 = mrow + i * 16 + g, r1 = r0 + 8;
            int n = cb + nl;
            int ch = n >> 5, kp = (n & 31) >> 1;
            size_t base = ((size_t)bx * 8 + ch) * 2048;
            R1f[base + afrag_off(r0, kp)] = pack_h2(v00, v01);
            R1f[base + afrag_off(r1, kp)] = pack_h2(v10, v11);
        }
}

// ---- router GEMM2 + logits + gumbel softmax -> weights ---------------------
__global__ __launch_bounds__(256)
void router23_f16(const uint32_t* __restrict__ R1f, const uint32_t* __restrict__ Wp,
                  const float* __restrict__ rb2, const float* __restrict__ rw3,
                  const float* __restrict__ rb3, const float* __restrict__ u,
                  float* __restrict__ weights) {
    extern __shared__ uint32_t sm[];
    float* bs   = (float*)(sm + 24576);  // 128
    float* b3   = (float*)(sm + 24704);  // 16
    float* w3s  = (float*)(sm + 24720);  // 1280
    float* zbuf = (float*)(sm + 26000);  // 2560
    uint32_t ring = (uint32_t)__cvta_generic_to_shared(sm);

    const int tid = threadIdx.x, lane = tid & 31, wid = tid >> 5;
    const int bx = blockIdx.x, rb = bx * 128;
    const int mtg = (wid & 3) * 2, ntg = (wid >> 2) * 8;
    if (tid < 128) bs[tid] = rb2[tid];
    if (tid < E_)  b3[tid] = rb3[tid];
    for (int i = tid; i < RH2_ * E_; i += 256) w3s[i] = rw3[i];

    float acc[2][8][4];
#pragma unroll
    for (int i = 0; i < 2; i++)
#pragma unroll
        for (int j = 0; j < 8; j++)
#pragma unroll
            for (int q = 0; q < 4; q++) acc[i][j][q] = 0.f;

    gemm_pipe2(ring, R1f + (size_t)bx * 8 * 2048, Wp, sm, 4, acc, mtg, ntg, lane, tid);

    const int g = lane >> 2, tig = lane & 3;
    const int mrow = (wid & 3) * 32, nh = wid >> 2;
    float zp[2][2][E_];
#pragma unroll
    for (int i = 0; i < 2; i++)
#pragma unroll
        for (int h = 0; h < 2; h++)
#pragma unroll
            for (int e = 0; e < E_; e++) zp[i][h][e] = 0.f;

#pragma unroll
    for (int j = 0; j < 8; j++) {
        int nl0 = nh * 64 + j * 8 + 2 * tig, nl1 = nl0 + 1;
        float wA[E_], wB[E_];
#pragma unroll
        for (int e = 0; e < E_; e++) { wA[e] = w3s[nl0 * E_ + e]; wB[e] = w3s[nl1 * E_ + e]; }
#pragma unroll
        for (int i = 0; i < 2; i++) {
            float v00 = fmaxf(acc[i][j][0] + bs[nl0], 0.f);
            float v01 = fmaxf(acc[i][j][1] + bs[nl1], 0.f);
            float v10 = fmaxf(acc[i][j][2] + bs[nl0], 0.f);
            float v11 = fmaxf(acc[i][j][3] + bs[nl1], 0.f);
#pragma unroll
            for (int e = 0; e < E_; e++) {
                zp[i][0][e] += v00 * wA[e] + v01 * wB[e];
                zp[i][1][e] += v10 * wA[e] + v11 * wB[e];
            }
        }
    }
#pragma unroll
    for (int i = 0; i < 2; i++)
#pragma unroll
        for (int h = 0; h < 2; h++)
#pragma unroll
            for (int e = 0; e < E_; e++) {
                zp[i][h][e] += __shfl_xor_sync(0xFFFFFFFFu, zp[i][h][e], 1);
                zp[i][h][e] += __shfl_xor_sync(0xFFFFFFFFu, zp[i][h][e], 2);
            }
    if (tig == 0) {
#pragma unroll
        for (int i = 0; i < 2; i++)
#pragma unroll
            for (int h = 0; h < 2; h++) {
                int row = mrow + i * 16 + h * 8 + g;
#pragma unroll
                for (int e = 0; e < E_; e++)
                    zbuf[(nh * 128 + row) * E_ + e] = zp[i][h][e];
            }
    }
    __syncthreads();
    if (tid < 128) {
        int b = rb + tid;
        float lg[E_], mx = -1e30f;
#pragma unroll
        for (int e = 0; e < E_; e++) {
            float uu = u[(size_t)b * E_ + e];
            uu = fminf(fmaxf(uu, 1e-10f), 1.0f);
            float gg = -logf(-logf(uu) + 1e-10f);
            lg[e] = (zbuf[tid * E_ + e] + zbuf[(128 + tid) * E_ + e] + b3[e] + gg)
                    * (1.0f / 3.0f);
            mx = fmaxf(mx, lg[e]);
        }
        float sum = 0.f;
#pragma unroll
        for (int e = 0; e < E_; e++) { lg[e] = expf(lg[e] - mx); sum += lg[e]; }
        float inv = 1.f / sum;
#pragma unroll
        for (int e = 0; e < E_; e++) weights[(size_t)b * E_ + e] = lg[e] * inv;
    }
}

// ---- fused expert chain (paired pipeline, BM=128) --------------------------
// smem u32 map: [0..24576) ring (3 groups x 8192)
//   after GEMM1: w2 chunks at u32 [0..8192), H1 at u32 [8192..16384)
__global__ __launch_bounds__(256)
void expert_f16(const uint32_t* __restrict__ Xp, const uint32_t* __restrict__ Wp,
                const float* __restrict__ eb1, const float* __restrict__ eb2,
                const float* __restrict__ ew3, const float* __restrict__ eb3,
                float* __restrict__ chart) {
    extern __shared__ uint32_t sm[];
    uint32_t* H1 = sm + 8192;
    float* b1s  = (float*)(sm + 24576);   // 128
    float* b2s  = (float*)(sm + 24704);   // 128
    float* w3s  = (float*)(sm + 24832);   // 256
    float* zbuf = (float*)(sm + 25088);   // 512
    uint32_t ring = (uint32_t)__cvta_generic_to_shared(sm);

    const int tid = threadIdx.x, lane = tid & 31, wid = tid >> 5;
    const int e = blockIdx.y, bx = blockIdx.x, rb = bx * 128;
    const int mtg = (wid & 3) * 2, ntg = (wid >> 2) * 8;
    const int g = lane >> 2, tig = lane & 3;
    const int mrow = (wid & 3) * 32, nh = wid >> 2;

    if (tid < 128) {
        b1s[tid] = eb1[e * H_ + tid];
        b2s[tid] = eb2[e * H_ + tid];
        w3s[tid] = ew3[e * H_ * L_ + tid];
        w3s[tid + 128] = ew3[e * H_ * L_ + 128 + tid];
    }

    const uint32_t* xb  = Xp + (size_t)bx * 16 * 2048;
    const uint32_t* w1b = Wp + EW1_OFF + (size_t)e * 32768;
    const uint32_t* w2b = Wp + EW2_OFF + (size_t)e * 8192;

    float acc[2][8][4];
#pragma unroll
    for (int i = 0; i < 2; i++)
#pragma unroll
        for (int j = 0; j < 8; j++)
#pragma unroll
            for (int q = 0; q < 4; q++) acc[i][j][q] = 0.f;

    // ---- GEMM1: x[128,512] @ w1, 8 paired iterations ----
    gemm_pipe2(ring, xb, w1b, sm, 8, acc, mtg, ntg, lane, tid);

    __syncthreads();   // all warps done with ring

    // prefetch all 4 w2 chunks into group-0 area, overlapping epilogue1
#pragma unroll
    for (int c = 0; c < 4; c++)
        issue_chunk(ring + c * 8192, w2b + c * 2048, tid);
    CP_COMMIT();

    // ---- epilogue1: h1 = relu(acc + b1) -> H1 (group-1 area) ----
#pragma unroll
    for (int i = 0; i < 2; i++)
#pragma unroll
        for (int j = 0; j < 8; j++) {
            int nl = nh * 64 + j * 8 + 2 * tig;
            float v00 = fmaxf(acc[i][j][0] + b1s[nl], 0.f);
            float v01 = fmaxf(acc[i][j][1] + b1s[nl + 1], 0.f);
            float v10 = fmaxf(acc[i][j][2] + b1s[nl], 0.f);
            float v11 = fmaxf(acc[i][j][3] + b1s[nl + 1], 0.f);
            int r0 = mrow + i * 16 + g, r1 = r0 + 8;
            int ch = nl >> 5, kp = (nl & 31) >> 1;
            H1[ch * 2048 + afrag_off(r0, kp)] = pack_h2(v00, v01);
            H1[ch * 2048 + afrag_off(r1, kp)] = pack_h2(v10, v11);
        }

#pragma unroll
    for (int i = 0; i < 2; i++)
#pragma unroll
        for (int j = 0; j < 8; j++)
#pragma unroll
            for (int q = 0; q < 4; q++) acc[i][j][q] = 0.f;

    CP_WAIT0();
    __syncthreads();   // H1 + w2 visible to all

    // ---- GEMM2: h1[128,128] @ w2, 4 chunks, no intervening syncs ----
#pragma unroll
    for (int c = 0; c < 4; c++)
        compute_bk(H1 + c * 2048, sm + c * 2048, acc, mtg, ntg, lane);

    // ---- epilogue2 + GEMM3: zc = relu(acc + b2) @ w3 + b3 ----
    {
        float zp[2][2][2];
#pragma unroll
        for (int i = 0; i < 2; i++)
#pragma unroll
            for (int h = 0; h < 2; h++) { zp[i][h][0] = 0.f; zp[i][h][1] = 0.f; }
#pragma unroll
        for (int i = 0; i < 2; i++)
#pragma unroll
            for (int j = 0; j < 8; j++) {
                int nl0 = nh * 64 + j * 8 + 2 * tig, nl1 = nl0 + 1;
                float h00 = fmaxf(acc[i][j][0] + b2s[nl0], 0.f);
                float h01 = fmaxf(acc[i][j][1] + b2s[nl1], 0.f);
                float h10 = fmaxf(acc[i][j][2] + b2s[nl0], 0.f);
                float h11 = fmaxf(acc[i][j][3] + b2s[nl1], 0.f);
                float w00 = w3s[nl0 * 2], w01 = w3s[nl0 * 2 + 1];
                float w10 = w3s[nl1 * 2], w11 = w3s[nl1 * 2 + 1];
                zp[i][0][0] += h00 * w00 + h01 * w10;
                zp[i][0][1] += h00 * w01 + h01 * w11;
                zp[i][1][0] += h10 * w00 + h11 * w10;
                zp[i][1][1] += h10 * w01 + h11 * w11;
            }
#pragma unroll
        for (int i = 0; i < 2; i++)
#pragma unroll
            for (int h = 0; h < 2; h++)
#pragma unroll
                for (int l = 0; l < 2; l++) {
                    zp[i][h][l] += __shfl_xor_sync(0xFFFFFFFFu, zp[i][h][l], 1);
                    zp[i][h][l] += __shfl_xor_sync(0xFFFFFFFFu, zp[i][h][l], 2);
                }
        if (tig == 0) {
#pragma unroll
            for (int i = 0; i < 2; i++)
#pragma unroll
                for (int h = 0; h < 2; h++) {
                    int row = mrow + i * 16 + h * 8 + g;
                    zbuf[(nh * 128 + row) * 2]     = zp[i][h][0];
                    zbuf[(nh * 128 + row) * 2 + 1] = zp[i][h][1];
                }
        }
        __syncthreads();
        if (tid < 128) {
            float s0 = zbuf[tid * 2]     + zbuf[(128 + tid) * 2]     + eb3[e * 2];
            float s1 = zbuf[tid * 2 + 1] + zbuf[(128 + tid) * 2 + 1] + eb3[e * 2 + 1];
            *(float2*)&chart[((size_t)e * B_ + rb + tid) * 2] = make_float2(s0, s1);
        }
    }
}

__global__ __launch_bounds__(256)
void z_combine(const float* __restrict__ weights, const float* __restrict__ chart,
               float* __restrict__ z) {
    int idx = blockIdx.x * blockDim.x + threadIdx.x;
    int b = idx >> 1, l = idx & 1;
    float s = 0.f;
#pragma unroll
    for (int e = 0; e < E_; e++)
        s += weights[(size_t)b * E_ + e] * chart[((size_t)e * B_ + b) * L_ + l];
    z[idx] = s;
}

// ---------------------------------------------------------------------------
extern "C" void kernel_launch(void* const* d_in, const int* in_sizes, int n_in,
                              void* d_out, int out_size) {
    const float* x   = (const float*)d_in[0];
    const float* u   = (const float*)d_in[1];
    const float* rw1 = (const float*)d_in[2];
    const float* rb1 = (const float*)d_in[3];
    const float* rw2 = (const float*)d_in[4];
    const float* rb2 = (const float*)d_in[5];
    const float* rw3 = (const float*)d_in[6];
    const float* rb3 = (const float*)d_in[7];
    const float* ew1 = (const float*)d_in[8];
    const float* eb1 = (const float*)d_in[9];
    const float* ew2 = (const float*)d_in[10];
    const float* eb2 = (const float*)d_in[11];
    const float* ew3 = (const float*)d_in[12];
    const float* eb3 = (const float*)d_in[13];

    float* out     = (float*)d_out;
    float* z       = out;
    float* weights = out + (size_t)B_ * L_;
    float* chart   = weights + (size_t)B_ * E_;

    uint32_t *Xp, *Wf, *R1f;
    cudaGetSymbolAddress((void**)&Xp,  g_Xp);
    cudaGetSymbolAddress((void**)&Wf,  g_Wf);
    cudaGetSymbolAddress((void**)&R1f, g_R1f);

    const int R1_SMEM = 24704 * 4;    // ring 96K + bias
    const int R2_SMEM = 28560 * 4;    // ring 96K + bias/w3/zbuf
    const int EX_SMEM = 25600 * 4;    // ring 96K + biases/w3 + 512-float zbuf (FIX)
    cudaFuncSetAttribute(router1_f16,  cudaFuncAttributeMaxDynamicSharedMemorySize, R1_SMEM);
    cudaFuncSetAttribute(router23_f16, cudaFuncAttributeMaxDynamicSharedMemorySize, R2_SMEM);
    cudaFuncSetAttribute(expert_f16,   cudaFuncAttributeMaxDynamicSharedMemorySize, EX_SMEM);

    static cudaStream_t s2 = nullptr;
    static cudaEvent_t evFork = nullptr, evJoin = nullptr;
    if (s2 == nullptr) {
        cudaStreamCreateWithFlags(&s2, cudaStreamNonBlocking);
        cudaEventCreateWithFlags(&evFork, cudaEventDisableTiming);
        cudaEventCreateWithFlags(&evJoin, cudaEventDisableTiming);
    }

    prep_all<<<1920 + 4096, 256>>>(x, rw1, rw2, ew1, ew2, Xp, Wf);

    // Fork: router chain on s2, expert on main stream (independent work).
    cudaEventRecord(evFork, 0);
    cudaStreamWaitEvent(s2, evFork, 0);
    router1_f16<<<dim3(256, 2), 256, R1_SMEM, s2>>>(Xp, Wf + RW1_OFF, rb1, R1f);
    router23_f16<<<256, 256, R2_SMEM, s2>>>(R1f, Wf + RW2_OFF, rb2, rw3, rb3, u, weights);
    cudaEventRecord(evJoin, s2);

    expert_f16<<<dim3(256, E_), 256, EX_SMEM>>>(Xp, Wf, eb1, eb2, ew3, eb3, chart);

    // Join: z_combine needs both weights (s2) and chart (main).
    cudaStreamWaitEvent(0, evJoin, 0);
    z_combine<<<(B_ * L_) / 256, 256>>>(weights, chart, z);
}